// round 13
// baseline (speedup 1.0000x reference)
#include <cuda_runtime.h>
#include <cuda_bf16.h>
#include <math.h>
#include <stdint.h>

// Problem constants
#define BB 2048
#define DD 512
#define NN 64
#define MM 32
// DECAY=0.97 AGE_INC=0.02 TEMP=0.5

// ---------------- scratch (static device globals; no allocation) -------------
__device__ float g_base[BB * 2 * DD];   // [b][0..511]=base_key, [512..1023]=base_value
__device__ float g_cv[BB * DD];         // candidate_value (tanh'd)
__device__ float g_kf[BB];              // key_focus
__device__ float g_cp[BB];              // compactness
__device__ float g_pers[BB];            // persistence
__device__ float g_cons[BB];            // consolidation
__device__ int   g_src[BB];             // episodic argmax index
__device__ int   g_i1[BB], g_i2[BB], g_tg[BB];
__device__ float g_w1[BB], g_w2[BB], g_ovm[BB];

__device__ __forceinline__ float wred(float v) {
    #pragma unroll
    for (int o = 16; o; o >>= 1) v += __shfl_down_sync(0xffffffffu, v, o);
    return v;
}
__device__ __forceinline__ float sigmoidf_(float x) { return 1.f / (1.f + expf(-x)); }
__device__ __forceinline__ float clip01(float x) { return fminf(fmaxf(x, 0.f), 1.f); }

__device__ __forceinline__ float to_tf32(float x) {
    uint32_t u;
    asm("cvt.rna.tf32.f32 %0, %1;" : "=r"(u) : "f"(x));
    return __uint_as_float(u);
}
__device__ __forceinline__ void mma_tf32(float c[4],
    uint32_t a0, uint32_t a1, uint32_t a2, uint32_t a3,
    uint32_t b0, uint32_t b1)
{
    asm volatile(
        "mma.sync.aligned.m16n8k8.row.col.f32.tf32.tf32.f32 "
        "{%0,%1,%2,%3}, {%4,%5,%6,%7}, {%8,%9}, {%0,%1,%2,%3};"
        : "+f"(c[0]), "+f"(c[1]), "+f"(c[2]), "+f"(c[3])
        : "r"(a0), "r"(a1), "r"(a2), "r"(a3), "r"(b0), "r"(b1));
}

// ============================================================================
// K1: g_base[b][outOff+j] = tanh( joined[b,:] . W[j,:] + bias[j] )
// Block tile 128M x 128N x 16K, 256 threads (8 warps 2x4), warp 64M x 32N.
// RES=true : 3-term TF32 split (key half, feeds decisions — high precision)
// RES=false: single TF32 (value half, continuous-only outputs)
// ============================================================================
#define K1S 20                 // padded row stride (floats)
#define K1_PLANE (128 * K1S)   // 2560 floats per buffer plane

template<bool RES>
__global__ __launch_bounds__(256) void k1_gemm(
    const float* __restrict__ signal, const float* __restrict__ hidden,
    const float* __restrict__ W,      const float* __restrict__ bias,
    int outOff)
{
    extern __shared__ __align__(16) float sm[];
    // floats: Ab[2]@0, Ar[2]@5120, Bb[2]@10240, Br[2]@15360, total 20480
    const int tid = threadIdx.x;
    const int lane = tid & 31, wid = tid >> 5;
    const int g = lane >> 2, tig = lane & 3;
    const int warp_m = wid & 1, warp_n = wid >> 1;

    const int rowBase = blockIdx.y * 128;
    const int cl = blockIdx.x * 128;     // local column within this half

    float acc[4][4][4];
    #pragma unroll
    for (int mt = 0; mt < 4; mt++)
        #pragma unroll
        for (int nt = 0; nt < 4; nt++)
            #pragma unroll
            for (int i = 0; i < 4; i++) acc[mt][nt][i] = 0.f;

    float4 pa[2], pbv[2];

    // prefetch kt=0
    #pragma unroll
    for (int i = 0; i < 2; i++) {
        int f = tid + i * 256;
        int r = f >> 2, kk = (f & 3) * 4;
        pa[i]  = *(const float4*)(signal + (size_t)(rowBase + r) * DD + kk);
        pbv[i] = *(const float4*)(W + (size_t)(cl + r) * (2 * DD) + kk);
    }
    // stage buf 0
    {
        float* Ab = sm;            float* Ar = sm + 5120;
        float* Bb = sm + 10240;    float* Br = sm + 15360;
        #pragma unroll
        for (int i = 0; i < 2; i++) {
            int f = tid + i * 256;
            int r = f >> 2, kk = (f & 3) * 4;
            float4 v = pa[i];
            float4 bg;
            bg.x = to_tf32(v.x); bg.y = to_tf32(v.y); bg.z = to_tf32(v.z); bg.w = to_tf32(v.w);
            *(float4*)(Ab + r * K1S + kk) = bg;
            if (RES) {
                float4 rs;
                rs.x = v.x - bg.x; rs.y = v.y - bg.y; rs.z = v.z - bg.z; rs.w = v.w - bg.w;
                *(float4*)(Ar + r * K1S + kk) = rs;
            }
            v = pbv[i];
            bg.x = to_tf32(v.x); bg.y = to_tf32(v.y); bg.z = to_tf32(v.z); bg.w = to_tf32(v.w);
            *(float4*)(Bb + r * K1S + kk) = bg;
            if (RES) {
                float4 rs;
                rs.x = v.x - bg.x; rs.y = v.y - bg.y; rs.z = v.z - bg.z; rs.w = v.w - bg.w;
                *(float4*)(Br + r * K1S + kk) = rs;
            }
        }
    }
    __syncthreads();

    int buf = 0;
    for (int kt = 0; kt < 2 * DD; kt += 16) {
        const bool has = (kt + 16) < 2 * DD;
        if (has) {
            const int ktn = kt + 16;
            #pragma unroll
            for (int i = 0; i < 2; i++) {
                int f = tid + i * 256;
                int r = f >> 2, kk = (f & 3) * 4;
                int gk = ktn + kk;
                const float* srcp = (ktn < DD)
                    ? (signal + (size_t)(rowBase + r) * DD + gk)
                    : (hidden + (size_t)(rowBase + r) * DD + (gk - DD));
                pa[i]  = *(const float4*)srcp;
                pbv[i] = *(const float4*)(W + (size_t)(cl + r) * (2 * DD) + ktn + kk);
            }
        }

        // compute from buf
        {
            const float* Abf = sm + buf * K1_PLANE;
            const float* Arf = sm + 5120 + buf * K1_PLANE;
            const float* Bbf = sm + 10240 + buf * K1_PLANE;
            const float* Brf = sm + 15360 + buf * K1_PLANE;
            #pragma unroll
            for (int ks = 0; ks < 16; ks += 8) {
                const int c0 = ks + tig;
                uint32_t ab[4][4], ar[4][4], bbf[4][2], brf[4][2];
                #pragma unroll
                for (int mt = 0; mt < 4; mt++) {
                    int r0 = warp_m * 64 + mt * 16 + g;
                    ab[mt][0] = __float_as_uint(Abf[r0 * K1S + c0]);
                    ab[mt][1] = __float_as_uint(Abf[(r0 + 8) * K1S + c0]);
                    ab[mt][2] = __float_as_uint(Abf[r0 * K1S + c0 + 4]);
                    ab[mt][3] = __float_as_uint(Abf[(r0 + 8) * K1S + c0 + 4]);
                    if (RES) {
                        ar[mt][0] = __float_as_uint(Arf[r0 * K1S + c0]);
                        ar[mt][1] = __float_as_uint(Arf[(r0 + 8) * K1S + c0]);
                        ar[mt][2] = __float_as_uint(Arf[r0 * K1S + c0 + 4]);
                        ar[mt][3] = __float_as_uint(Arf[(r0 + 8) * K1S + c0 + 4]);
                    }
                }
                #pragma unroll
                for (int nt = 0; nt < 4; nt++) {
                    int n0 = warp_n * 32 + nt * 8 + g;
                    bbf[nt][0] = __float_as_uint(Bbf[n0 * K1S + c0]);
                    bbf[nt][1] = __float_as_uint(Bbf[n0 * K1S + c0 + 4]);
                    if (RES) {
                        brf[nt][0] = __float_as_uint(Brf[n0 * K1S + c0]);
                        brf[nt][1] = __float_as_uint(Brf[n0 * K1S + c0 + 4]);
                    }
                }
                #pragma unroll
                for (int mt = 0; mt < 4; mt++)
                    #pragma unroll
                    for (int nt = 0; nt < 4; nt++) {
                        mma_tf32(acc[mt][nt], ab[mt][0], ab[mt][1], ab[mt][2], ab[mt][3],
                                 bbf[nt][0], bbf[nt][1]);
                        if (RES) {
                            mma_tf32(acc[mt][nt], ab[mt][0], ab[mt][1], ab[mt][2], ab[mt][3],
                                     brf[nt][0], brf[nt][1]);
                            mma_tf32(acc[mt][nt], ar[mt][0], ar[mt][1], ar[mt][2], ar[mt][3],
                                     bbf[nt][0], bbf[nt][1]);
                        }
                    }
            }
        }

        if (has) {
            float* Ab = sm + (buf ^ 1) * K1_PLANE;
            float* Ar = sm + 5120 + (buf ^ 1) * K1_PLANE;
            float* Bb = sm + 10240 + (buf ^ 1) * K1_PLANE;
            float* Br = sm + 15360 + (buf ^ 1) * K1_PLANE;
            #pragma unroll
            for (int i = 0; i < 2; i++) {
                int f = tid + i * 256;
                int r = f >> 2, kk = (f & 3) * 4;
                float4 v = pa[i];
                float4 bg;
                bg.x = to_tf32(v.x); bg.y = to_tf32(v.y); bg.z = to_tf32(v.z); bg.w = to_tf32(v.w);
                *(float4*)(Ab + r * K1S + kk) = bg;
                if (RES) {
                    float4 rs;
                    rs.x = v.x - bg.x; rs.y = v.y - bg.y; rs.z = v.z - bg.z; rs.w = v.w - bg.w;
                    *(float4*)(Ar + r * K1S + kk) = rs;
                }
                v = pbv[i];
                bg.x = to_tf32(v.x); bg.y = to_tf32(v.y); bg.z = to_tf32(v.z); bg.w = to_tf32(v.w);
                *(float4*)(Bb + r * K1S + kk) = bg;
                if (RES) {
                    float4 rs;
                    rs.x = v.x - bg.x; rs.y = v.y - bg.y; rs.z = v.z - bg.z; rs.w = v.w - bg.w;
                    *(float4*)(Br + r * K1S + kk) = rs;
                }
            }
            __syncthreads();
            buf ^= 1;
        }
    }

    // epilogue: bias + tanh
    const float* biasp = bias + cl;
    #pragma unroll
    for (int mt = 0; mt < 4; mt++) {
        int row = rowBase + warp_m * 64 + mt * 16 + g;
        #pragma unroll
        for (int nt = 0; nt < 4; nt++) {
            int cb = warp_n * 32 + nt * 8 + 2 * tig;
            float b0 = biasp[cb], b1 = biasp[cb + 1];
            int col = outOff + cl + cb;
            float2 p0, p1;
            p0.x = tanhf(acc[mt][nt][0] + b0);
            p0.y = tanhf(acc[mt][nt][1] + b1);
            p1.x = tanhf(acc[mt][nt][2] + b0);
            p1.y = tanhf(acc[mt][nt][3] + b1);
            *(float2*)&g_base[(size_t)row * (2 * DD) + col] = p0;
            *(float2*)&g_base[(size_t)(row + 8) * (2 * DD) + col] = p1;
        }
    }
}

// ============================================================================
// K2a: episodic priority + argmax + gate dots + scalar gates (k1-independent).
// ============================================================================
__global__ __launch_bounds__(256) void k2a_select(
    const float* __restrict__ ep_vals,
    const float* __restrict__ ep_str,  const float* __restrict__ ep_hits,
    const float* __restrict__ ep_age,
    const float* __restrict__ signal,  const float* __restrict__ hidden,
    const float* __restrict__ branch,  const float* __restrict__ entropy,
    const float* __restrict__ delay,
    const float* __restrict__ fgW, const float* __restrict__ fgb,
    const float* __restrict__ pgW, const float* __restrict__ pgb,
    const float* __restrict__ cgW, const float* __restrict__ cgb)
{
    const int b = blockIdx.x;
    const int tid = threadIdx.x;
    const int lane = tid & 31, w = tid >> 5;

    __shared__ float pr[MM];
    __shared__ float dots[3];
    __shared__ int   s_src;
    __shared__ float s_conf;

    #pragma unroll
    for (int mi = 0; mi < 4; mi++) {
        int m = w * 4 + mi;
        const float* row = ep_vals + ((size_t)b * MM + m) * DD;
        float ss = 0.f;
        #pragma unroll
        for (int j = 0; j < 4; j++) {
            float4 v = *(const float4*)(row + lane * 4 + j * 128);
            ss += v.x * v.x + v.y * v.y + v.z * v.z + v.w * v.w;
        }
        ss = wred(ss);
        if (lane == 0) {
            float epn = sqrtf(ss) * 0.0441941738f;   // /sqrt(512)
            pr[m] = 0.45f * ep_str[b * MM + m]
                  + 0.3f  * (ep_hits[b * MM + m] * (1.f / 6.f))
                  + 0.15f * (1.f - ep_age[b * MM + m])
                  + 0.1f  * clip01(epn);
        }
    }
    __syncthreads();

    if (w == 0) {
        float v = pr[lane]; int idx = lane;
        #pragma unroll
        for (int o = 16; o; o >>= 1) {
            float ov = __shfl_down_sync(0xffffffffu, v, o);
            int   oi = __shfl_down_sync(0xffffffffu, idx, o);
            if (ov > v || (ov == v && oi < idx)) { v = ov; idx = oi; }
        }
        if (lane == 0) { s_src = idx; s_conf = v; }
    }
    if (w >= 1 && w <= 3) {
        const float* Wg = (w == 1) ? fgW : (w == 2) ? pgW : cgW;
        float acc = 0.f;
        for (int i = lane; i < 2 * DD + 3; i += 32) {
            float r = (i < DD) ? signal[(size_t)b * DD + i]
                    : (i < 2 * DD) ? hidden[(size_t)b * DD + i - DD]
                    : branch[(size_t)b * 3 + (i - 2 * DD)];
            acc += r * Wg[i];
        }
        acc = wred(acc);
        if (lane == 0) dots[w - 1] = acc;
    }
    __syncthreads();

    if (tid == 0) {
        const float focus   = sigmoidf_(dots[0] + fgb[0]);
        const float pers    = sigmoidf_(dots[1] + pgb[0]);
        const float cons    = sigmoidf_(dots[2] + cgb[0] + 2.2f * (s_conf - 0.5f));
        const float compact = sigmoidf_((0.72f - entropy[b]) * 5.5f);
        const float kf      = clip01(0.45f * focus + 0.3f * compact + 0.25f * delay[b]);
        g_kf[b] = kf; g_cp[b] = compact; g_pers[b] = pers;
        g_cons[b] = cons; g_src[b] = s_src;
    }
}

// ============================================================================
// K2c: candidate_value only (needs val half of g_base + K2a). Side stream.
// ============================================================================
__global__ __launch_bounds__(256) void k2c_val(const float* __restrict__ ep_vals)
{
    const int b = blockIdx.x;
    const int tid = threadIdx.x;
    const float c = g_cons[b];
    const int src = g_src[b];
    const float* bv = g_base + (size_t)b * (2 * DD) + DD;
    const float* sv = ep_vals + ((size_t)b * MM + src) * DD;
    const float a = 1.f - 0.35f * c, s = 0.35f * c;
    #pragma unroll
    for (int o = 0; o < 2; o++) {
        int d = tid + o * 256;
        g_cv[(size_t)b * DD + d] = tanhf(a * bv[d] + s * sv[d]);
    }
}

// ============================================================================
// K3: candidate-key prologue + keys stream (read-once, write-through)
//     + all decisions + target key blend. Needs only k1_key + k2a.
// ============================================================================
__global__ __launch_bounds__(256) void k3_keys(
    const float* __restrict__ qk, const float* __restrict__ delay,
    const float* __restrict__ sal,
    const float* __restrict__ skeys, const float* __restrict__ ep_keys,
    const float* __restrict__ str_g, const float* __restrict__ age_g,
    const float* __restrict__ usg_g,
    float* __restrict__ out_hits, float* __restrict__ out_keys,
    float* __restrict__ out_str,  float* __restrict__ out_age,
    float* __restrict__ out_usg)
{
    __shared__ __align__(16) float sq[DD], sck[DD];
    __shared__ float scores[NN], sim[NN], repl[NN];
    __shared__ float sstr[NN], sage[NN], susg[NN];
    __shared__ float red[9];
    __shared__ float bc[6];
    __shared__ int   bci[3];

    const int b = blockIdx.x;
    const int tid = threadIdx.x;
    const int lane = tid & 31, w = tid >> 5;

    // ---- prologue: build candidate_key in sck (was k2b) ----
    {
        const float cns = g_cons[b];
        const int   es  = g_src[b];
        const float* bkp = g_base + (size_t)b * (2 * DD);
        const float* skp = ep_keys + ((size_t)b * MM + es) * DD;
        sq[tid]       = qk[(size_t)b * DD + tid];
        sq[tid + 256] = qk[(size_t)b * DD + tid + 256];
        float m0 = (1.f - cns) * bkp[tid]       + cns * skp[tid];
        float m1 = (1.f - cns) * bkp[tid + 256] + cns * skp[tid + 256];
        sck[tid] = m0; sck[tid + 256] = m1;
        float ssq = wred(m0 * m0 + m1 * m1);
        if (lane == 0) red[w] = ssq;
        if (tid < NN) {
            float s = str_g[b * NN + tid], a = age_g[b * NN + tid], u = usg_g[b * NN + tid];
            sstr[tid] = s; sage[tid] = a; susg[tid] = u;
            repl[tid] = 1.3f * a + (1.f - s) + 0.9f * (1.f - u);
        }
        __syncthreads();
        if (tid == 0) {
            float t = 0.f;
            #pragma unroll
            for (int i = 0; i < 8; i++) t += red[i];
            red[8] = 1.f / fmaxf(sqrtf(t), 1e-6f);
        }
        __syncthreads();
        const float invn = red[8];
        sck[tid]       *= invn;
        sck[tid + 256] *= invn;
        __syncthreads();
    }

    float4 qv[4], cvv[4];
    #pragma unroll
    for (int j = 0; j < 4; j++) {
        qv[j]  = ((const float4*)sq)[lane + j * 32];
        cvv[j] = ((const float4*)sck)[lane + j * 32];
    }

    const float4* kin = (const float4*)(skeys + (size_t)b * NN * DD);
    float4* kout = (float4*)(out_keys + (size_t)b * NN * DD);
    const float dg = delay[b], sg = sal[b];

    #pragma unroll
    for (int p = 0; p < 4; p++) {
        const int n0 = w * 8 + p * 2, n1 = n0 + 1;
        float4 r0[4], r1[4];
        #pragma unroll
        for (int j = 0; j < 4; j++) r0[j] = kin[n0 * 128 + lane + j * 32];
        #pragma unroll
        for (int j = 0; j < 4; j++) r1[j] = kin[n1 * 128 + lane + j * 32];
        #pragma unroll
        for (int j = 0; j < 4; j++) kout[n0 * 128 + lane + j * 32] = r0[j];
        #pragma unroll
        for (int j = 0; j < 4; j++) kout[n1 * 128 + lane + j * 32] = r1[j];

        float ss0 = 0.f, dq0 = 0.f, dc0 = 0.f, ss1 = 0.f, dq1 = 0.f, dc1 = 0.f;
        #pragma unroll
        for (int j = 0; j < 4; j++) {
            ss0 += r0[j].x * r0[j].x + r0[j].y * r0[j].y + r0[j].z * r0[j].z + r0[j].w * r0[j].w;
            dq0 += r0[j].x * qv[j].x + r0[j].y * qv[j].y + r0[j].z * qv[j].z + r0[j].w * qv[j].w;
            dc0 += r0[j].x * cvv[j].x + r0[j].y * cvv[j].y + r0[j].z * cvv[j].z + r0[j].w * cvv[j].w;
            ss1 += r1[j].x * r1[j].x + r1[j].y * r1[j].y + r1[j].z * r1[j].z + r1[j].w * r1[j].w;
            dq1 += r1[j].x * qv[j].x + r1[j].y * qv[j].y + r1[j].z * qv[j].z + r1[j].w * qv[j].w;
            dc1 += r1[j].x * cvv[j].x + r1[j].y * cvv[j].y + r1[j].z * cvv[j].z + r1[j].w * cvv[j].w;
        }
        ss0 = wred(ss0); dq0 = wred(dq0); dc0 = wred(dc0);
        ss1 = wred(ss1); dq1 = wred(dq1); dc1 = wred(dc1);
        if (lane == 0) {
            float inv0 = 1.f / fmaxf(sqrtf(ss0), 1e-6f);
            float inv1 = 1.f / fmaxf(sqrtf(ss1), 1e-6f);
            sim[n0] = dc0 * inv0;
            sim[n1] = dc1 * inv1;
            float pr0 = 2.8f * sstr[n0] + 0.9f * susg[n0] + 0.6f * (1.f - sage[n0]);
            float pr1 = 2.8f * sstr[n1] + 0.9f * susg[n1] + 0.6f * (1.f - sage[n1]);
            scores[n0] = 0.65f * dq0 * inv0 + 0.22f * pr0 + 0.08f * dg * sage[n0] + 0.05f * sg * sstr[n0];
            scores[n1] = 0.65f * dq1 * inv1 + 0.22f * pr1 + 0.08f * dg * sage[n1] + 0.05f * sg * sstr[n1];
        }
    }
    __syncthreads();

    if (tid == 0) {
        int i1 = 0;
        for (int n = 1; n < NN; n++) if (scores[n] > scores[i1]) i1 = n;
        int i2 = -1;
        for (int n = 0; n < NN; n++) {
            if (n == i1) continue;
            if (i2 < 0 || scores[n] > scores[i2]) i2 = n;
        }
        float w1 = 1.f / (1.f + expf((scores[i2] - scores[i1]) * 2.f)); // TEMP=0.5
        float w2 = 1.f - w1;
        int mi = 0;
        for (int n = 1; n < NN; n++) if (sim[n] > sim[mi]) mi = n;
        int ri = 0;
        for (int n = 1; n < NN; n++) if (repl[n] > repl[ri]) ri = n;
        bool um = sim[mi] > 0.81f;
        int target = um ? mi : ri;
        float kf = g_kf[b], cp = g_cp[b], p = g_pers[b];
        float ow = (0.1f + 0.8f * kf) * (0.55f + 0.45f * cp);
        float kmix = um ? (0.18f + 0.24f * p) : (0.78f + 0.1f * p);
        float vmix = um ? (0.34f + 0.22f * p) : (0.82f + 0.1f * p);
        bc[0] = w1; bc[1] = w2; bc[2] = ow * kmix; bc[3] = ow; bc[4] = kf; bc[5] = p;
        bci[0] = i1; bci[1] = i2; bci[2] = target;
        g_i1[b] = i1; g_i2[b] = i2; g_tg[b] = target;
        g_w1[b] = w1; g_w2[b] = w2; g_ovm[b] = ow * vmix;
    }
    __syncthreads();

    const float w1 = bc[0], w2 = bc[1], owk = bc[2], ow = bc[3], kf = bc[4], p = bc[5];
    const int i1 = bci[0], i2 = bci[1], target = bci[2];

    if (tid < NN) {
        int n = tid;
        out_hits[(size_t)b * NN + n] = (n == i1) ? w1 : (n == i2) ? w2 : 0.f;
        float own = (n == target) ? ow : 0.f;
        out_str[(size_t)b * NN + n] = clip01(sstr[n] * 0.97f + own * (0.55f + 0.2f * kf + 0.15f * p));
        out_usg[(size_t)b * NN + n] = clip01(susg[n] * 0.96f + own * (0.6f + 0.4f * dg));
        out_age[(size_t)b * NN + n] = clip01((sage[n] + 0.02f) * (1.f - 0.85f * own));
    }

    if (tid >= 128) {
        int t = tid - 128;
        float4 v = kin[target * 128 + t];       // L2-hot
        float4 c = ((const float4*)sck)[t];
        v.x += owk * (c.x - v.x);
        v.y += owk * (c.y - v.y);
        v.z += owk * (c.z - v.z);
        v.w += owk * (c.w - v.w);
        kout[target * 128 + t] = v;
    }
}

// ============================================================================
// K4a: pure values copy (no dependencies — side stream). Deep MLP (8 in flight).
// ============================================================================
__global__ __launch_bounds__(256) void k4a_copy(
    const float* __restrict__ svals, float* __restrict__ out_vals)
{
    const int b = blockIdx.x;
    const int tid = threadIdx.x;
    const float4* src = (const float4*)(svals + (size_t)b * NN * DD);
    float4* dst = (float4*)(out_vals + (size_t)b * NN * DD);
    #pragma unroll
    for (int o = 0; o < 4; o++) {
        int i = tid + o * 2048;
        float4 v[8];
        #pragma unroll
        for (int j = 0; j < 8; j++) v[j] = src[i + j * 256];
        #pragma unroll
        for (int j = 0; j < 8; j++) dst[i + j * 256] = v[j];
    }
}

// ============================================================================
// K4b: target value-row blend + read_out (after K3, K4a, K2c).
// ============================================================================
__global__ __launch_bounds__(256) void k4b_fixup(
    const float* __restrict__ svals,
    float* __restrict__ out_vals, float* __restrict__ out_read)
{
    const int b = blockIdx.x;
    const int tid = threadIdx.x;
    const float4* src = (const float4*)(svals + (size_t)b * NN * DD);
    float4* dst = (float4*)(out_vals + (size_t)b * NN * DD);

    if (tid < 128) {
        const int target = g_tg[b];
        const float ovm = g_ovm[b];
        float4 v = src[target * 128 + tid];
        float4 c = ((const float4*)(g_cv + (size_t)b * DD))[tid];
        v.x += ovm * (c.x - v.x);
        v.y += ovm * (c.y - v.y);
        v.z += ovm * (c.z - v.z);
        v.w += ovm * (c.w - v.w);
        dst[target * 128 + tid] = v;
    } else {
        const int t = tid - 128;
        const int i1 = g_i1[b], i2 = g_i2[b];
        const float w1 = g_w1[b], w2 = g_w2[b];
        float4 a = src[i1 * 128 + t];
        float4 c2 = src[i2 * 128 + t];
        float4 o;
        o.x = w1 * a.x + w2 * c2.x;
        o.y = w1 * a.y + w2 * c2.y;
        o.z = w1 * a.z + w2 * c2.z;
        o.w = w1 * a.w + w2 * c2.w;
        ((float4*)(out_read + (size_t)b * DD))[t] = o;
    }
}

// ============================================================================
extern "C" void kernel_launch(void* const* d_in, const int* in_sizes, int n_in,
                              void* d_out, int out_size)
{
    const float* query_key   = (const float*)d_in[0];
    const float* delay_gate  = (const float*)d_in[1];
    const float* sal_gate    = (const float*)d_in[2];
    const float* short_keys  = (const float*)d_in[3];
    const float* short_vals  = (const float*)d_in[4];
    const float* short_str   = (const float*)d_in[5];
    const float* short_age   = (const float*)d_in[6];
    const float* short_usg   = (const float*)d_in[7];
    const float* signal      = (const float*)d_in[8];
    const float* hidden      = (const float*)d_in[9];
    const float* branch      = (const float*)d_in[10];
    const float* entropy     = (const float*)d_in[11];
    const float* ep_keys     = (const float*)d_in[12];
    const float* ep_vals     = (const float*)d_in[13];
    const float* ep_str      = (const float*)d_in[14];
    const float* ep_hits     = (const float*)d_in[15];
    const float* ep_age      = (const float*)d_in[16];
    const float* key_W       = (const float*)d_in[17];
    const float* key_b       = (const float*)d_in[18];
    const float* val_W       = (const float*)d_in[19];
    const float* val_b       = (const float*)d_in[20];
    const float* fg_W        = (const float*)d_in[21];
    const float* fg_b        = (const float*)d_in[22];
    const float* pg_W        = (const float*)d_in[23];
    const float* pg_b        = (const float*)d_in[24];
    const float* cg_W        = (const float*)d_in[25];
    const float* cg_b        = (const float*)d_in[26];

    float* out = (float*)d_out;
    float* o_read = out;                              // B*D
    float* o_hits = o_read + (size_t)BB * DD;         // B*N
    float* o_keys = o_hits + (size_t)BB * NN;         // B*N*D
    float* o_vals = o_keys + (size_t)BB * NN * DD;    // B*N*D
    float* o_str  = o_vals + (size_t)BB * NN * DD;    // B*N
    float* o_age  = o_str  + (size_t)BB * NN;         // B*N
    float* o_usg  = o_age  + (size_t)BB * NN;         // B*N

    const int k1_smem = 20480 * (int)sizeof(float);   // 81920 B

    static bool init_done = false;
    static cudaStream_t sA, sB, sC;
    static cudaEvent_t e0, eA, eB, eC;
    if (!init_done) {
        cudaStreamCreateWithFlags(&sA, cudaStreamNonBlocking);
        cudaStreamCreateWithFlags(&sB, cudaStreamNonBlocking);
        cudaStreamCreateWithFlags(&sC, cudaStreamNonBlocking);
        cudaEventCreateWithFlags(&e0, cudaEventDisableTiming);
        cudaEventCreateWithFlags(&eA, cudaEventDisableTiming);
        cudaEventCreateWithFlags(&eB, cudaEventDisableTiming);
        cudaEventCreateWithFlags(&eC, cudaEventDisableTiming);
        cudaFuncSetAttribute(k1_gemm<true>,
                             cudaFuncAttributeMaxDynamicSharedMemorySize, k1_smem);
        cudaFuncSetAttribute(k1_gemm<false>,
                             cudaFuncAttributeMaxDynamicSharedMemorySize, k1_smem);
        init_done = true;
    }

    // fork
    cudaEventRecord(e0, 0);
    cudaStreamWaitEvent(sA, e0, 0);
    cudaStreamWaitEvent(sB, e0, 0);
    cudaStreamWaitEvent(sC, e0, 0);

    // critical path: key-half GEMM first (3-term split, feeds all decisions)
    dim3 gk(DD / 128, BB / 128);   // (4, 16) = 64 blocks
    k1_gemm<true><<<gk, 256, k1_smem>>>(signal, hidden, key_W, key_b, 0);

    // value-half GEMM (single tf32 — continuous-only outputs) on side stream
    k1_gemm<false><<<gk, 256, k1_smem, sC>>>(signal, hidden, val_W, val_b, DD);

    // independent work
    k2a_select<<<BB, 256, 0, sB>>>(ep_vals, ep_str, ep_hits, ep_age,
                                   signal, hidden, branch, entropy, delay_gate,
                                   fg_W, fg_b, pg_W, pg_b, cg_W, cg_b);
    cudaEventRecord(eB, sB);

    k4a_copy<<<BB, 256, 0, sA>>>(short_vals, o_vals);
    cudaEventRecord(eA, sA);

    // candidate_value on sC (needs k1_val [same stream] + k2a)
    cudaStreamWaitEvent(sC, eB, 0);
    k2c_val<<<BB, 256, 0, sC>>>(ep_vals);
    cudaEventRecord(eC, sC);

    // main: k3 needs k1_key (same stream) + k2a
    cudaStreamWaitEvent(0, eB, 0);
    k3_keys<<<BB, 256>>>(query_key, delay_gate, sal_gate, short_keys, ep_keys,
                         short_str, short_age, short_usg,
                         o_hits, o_keys, o_str, o_age, o_usg);

    // join copy + candidate_value, then fix up target row + read_out
    cudaStreamWaitEvent(0, eA, 0);
    cudaStreamWaitEvent(0, eC, 0);
    k4b_fixup<<<BB, 256>>>(short_vals, o_vals, o_read);
}

// round 14
// speedup vs baseline: 1.0715x; 1.0715x over previous
#include <cuda_runtime.h>
#include <cuda_bf16.h>
#include <math.h>
#include <stdint.h>

// Problem constants
#define BB 2048
#define DD 512
#define NN 64
#define MM 32
// DECAY=0.97 AGE_INC=0.02 TEMP=0.5

// ---------------- scratch (static device globals; no allocation) -------------
__device__ float g_base[BB * 2 * DD];   // [b][0..511]=base_key, [512..1023]=base_value
__device__ float g_cv[BB * DD];         // candidate_value (tanh'd)
__device__ float g_kf[BB];              // key_focus
__device__ float g_cp[BB];              // compactness
__device__ float g_pers[BB];            // persistence
__device__ float g_cons[BB];            // consolidation
__device__ int   g_src[BB];             // episodic argmax index
__device__ int   g_i1[BB], g_i2[BB], g_tg[BB];
__device__ float g_w1[BB], g_w2[BB], g_ovm[BB];

__device__ __forceinline__ float wred(float v) {
    #pragma unroll
    for (int o = 16; o; o >>= 1) v += __shfl_down_sync(0xffffffffu, v, o);
    return v;
}
__device__ __forceinline__ float sigmoidf_(float x) { return 1.f / (1.f + expf(-x)); }
__device__ __forceinline__ float clip01(float x) { return fminf(fmaxf(x, 0.f), 1.f); }

__device__ __forceinline__ float to_tf32(float x) {
    uint32_t u;
    asm("cvt.rna.tf32.f32 %0, %1;" : "=r"(u) : "f"(x));
    return __uint_as_float(u);
}
__device__ __forceinline__ void mma_tf32(float c[4],
    uint32_t a0, uint32_t a1, uint32_t a2, uint32_t a3,
    uint32_t b0, uint32_t b1)
{
    asm volatile(
        "mma.sync.aligned.m16n8k8.row.col.f32.tf32.tf32.f32 "
        "{%0,%1,%2,%3}, {%4,%5,%6,%7}, {%8,%9}, {%0,%1,%2,%3};"
        : "+f"(c[0]), "+f"(c[1]), "+f"(c[2]), "+f"(c[3])
        : "r"(a0), "r"(a1), "r"(a2), "r"(a3), "r"(b0), "r"(b1));
}

// ============================================================================
// K1: g_base[b][outOff+j] = tanh( joined[b,:] . W[j,:] + bias[j] )
// Block tile 64M x 128N x 16K, 256 threads (8 warps 2x4), warp tile 32M x 32N.
// 128 blocks per half -> spreads across the chip (tensor floor ~27us key half).
// RES=true : 3-term TF32 split (key half, feeds decisions — high precision)
// RES=false: single TF32 (value half, continuous-only outputs)
// ============================================================================
#define K1S 20                   // padded row stride (floats)
#define K1_A_PLANE (64 * K1S)    // 1280 floats
#define K1_B_PLANE (128 * K1S)   // 2560 floats
// layout (floats): Ab[2]@0, Ar[2]@2560, Bb[2]@5120, Br[2]@10240, total 15360

template<bool RES>
__global__ __launch_bounds__(256) void k1_gemm(
    const float* __restrict__ signal, const float* __restrict__ hidden,
    const float* __restrict__ W,      const float* __restrict__ bias,
    int outOff)
{
    extern __shared__ __align__(16) float sm[];
    const int tid = threadIdx.x;
    const int lane = tid & 31, wid = tid >> 5;
    const int g = lane >> 2, tig = lane & 3;
    const int warp_m = wid & 1, warp_n = wid >> 1;

    const int rowBase = blockIdx.y * 64;
    const int cl = blockIdx.x * 128;     // local column within this half

    float acc[2][4][4];
    #pragma unroll
    for (int mt = 0; mt < 2; mt++)
        #pragma unroll
        for (int nt = 0; nt < 4; nt++)
            #pragma unroll
            for (int i = 0; i < 4; i++) acc[mt][nt][i] = 0.f;

    float4 pa, pbv[2];

    // prefetch kt=0
    {
        int r = tid >> 2, kk = (tid & 3) * 4;
        pa = *(const float4*)(signal + (size_t)(rowBase + r) * DD + kk);
        #pragma unroll
        for (int i = 0; i < 2; i++) {
            int f = tid + i * 256;
            int rb = f >> 2, kb = (f & 3) * 4;
            pbv[i] = *(const float4*)(W + (size_t)(cl + rb) * (2 * DD) + kb);
        }
    }
    // stage buf 0
    {
        float* Ab = sm;           float* Ar = sm + 2560;
        float* Bb = sm + 5120;    float* Br = sm + 10240;
        {
            int r = tid >> 2, kk = (tid & 3) * 4;
            float4 v = pa;
            float4 bg;
            bg.x = to_tf32(v.x); bg.y = to_tf32(v.y); bg.z = to_tf32(v.z); bg.w = to_tf32(v.w);
            *(float4*)(Ab + r * K1S + kk) = bg;
            if (RES) {
                float4 rs;
                rs.x = v.x - bg.x; rs.y = v.y - bg.y; rs.z = v.z - bg.z; rs.w = v.w - bg.w;
                *(float4*)(Ar + r * K1S + kk) = rs;
            }
        }
        #pragma unroll
        for (int i = 0; i < 2; i++) {
            int f = tid + i * 256;
            int r = f >> 2, kk = (f & 3) * 4;
            float4 v = pbv[i];
            float4 bg;
            bg.x = to_tf32(v.x); bg.y = to_tf32(v.y); bg.z = to_tf32(v.z); bg.w = to_tf32(v.w);
            *(float4*)(Bb + r * K1S + kk) = bg;
            if (RES) {
                float4 rs;
                rs.x = v.x - bg.x; rs.y = v.y - bg.y; rs.z = v.z - bg.z; rs.w = v.w - bg.w;
                *(float4*)(Br + r * K1S + kk) = rs;
            }
        }
    }
    __syncthreads();

    int buf = 0;
    for (int kt = 0; kt < 2 * DD; kt += 16) {
        const bool has = (kt + 16) < 2 * DD;
        if (has) {
            const int ktn = kt + 16;
            {
                int r = tid >> 2, kk = (tid & 3) * 4;
                int gk = ktn + kk;
                const float* srcp = (ktn < DD)
                    ? (signal + (size_t)(rowBase + r) * DD + gk)
                    : (hidden + (size_t)(rowBase + r) * DD + (gk - DD));
                pa = *(const float4*)srcp;
            }
            #pragma unroll
            for (int i = 0; i < 2; i++) {
                int f = tid + i * 256;
                int r = f >> 2, kk = (f & 3) * 4;
                pbv[i] = *(const float4*)(W + (size_t)(cl + r) * (2 * DD) + ktn + kk);
            }
        }

        // compute from buf
        {
            const float* Abf = sm + buf * K1_A_PLANE;
            const float* Arf = sm + 2560 + buf * K1_A_PLANE;
            const float* Bbf = sm + 5120 + buf * K1_B_PLANE;
            const float* Brf = sm + 10240 + buf * K1_B_PLANE;
            #pragma unroll
            for (int ks = 0; ks < 16; ks += 8) {
                const int c0 = ks + tig;
                uint32_t ab[2][4], ar[2][4], bbf[4][2], brf[4][2];
                #pragma unroll
                for (int mt = 0; mt < 2; mt++) {
                    int r0 = warp_m * 32 + mt * 16 + g;
                    ab[mt][0] = __float_as_uint(Abf[r0 * K1S + c0]);
                    ab[mt][1] = __float_as_uint(Abf[(r0 + 8) * K1S + c0]);
                    ab[mt][2] = __float_as_uint(Abf[r0 * K1S + c0 + 4]);
                    ab[mt][3] = __float_as_uint(Abf[(r0 + 8) * K1S + c0 + 4]);
                    if (RES) {
                        ar[mt][0] = __float_as_uint(Arf[r0 * K1S + c0]);
                        ar[mt][1] = __float_as_uint(Arf[(r0 + 8) * K1S + c0]);
                        ar[mt][2] = __float_as_uint(Arf[r0 * K1S + c0 + 4]);
                        ar[mt][3] = __float_as_uint(Arf[(r0 + 8) * K1S + c0 + 4]);
                    }
                }
                #pragma unroll
                for (int nt = 0; nt < 4; nt++) {
                    int n0 = warp_n * 32 + nt * 8 + g;
                    bbf[nt][0] = __float_as_uint(Bbf[n0 * K1S + c0]);
                    bbf[nt][1] = __float_as_uint(Bbf[n0 * K1S + c0 + 4]);
                    if (RES) {
                        brf[nt][0] = __float_as_uint(Brf[n0 * K1S + c0]);
                        brf[nt][1] = __float_as_uint(Brf[n0 * K1S + c0 + 4]);
                    }
                }
                #pragma unroll
                for (int mt = 0; mt < 2; mt++)
                    #pragma unroll
                    for (int nt = 0; nt < 4; nt++) {
                        mma_tf32(acc[mt][nt], ab[mt][0], ab[mt][1], ab[mt][2], ab[mt][3],
                                 bbf[nt][0], bbf[nt][1]);
                        if (RES) {
                            mma_tf32(acc[mt][nt], ab[mt][0], ab[mt][1], ab[mt][2], ab[mt][3],
                                     brf[nt][0], brf[nt][1]);
                            mma_tf32(acc[mt][nt], ar[mt][0], ar[mt][1], ar[mt][2], ar[mt][3],
                                     bbf[nt][0], bbf[nt][1]);
                        }
                    }
            }
        }

        if (has) {
            float* Ab = sm + (buf ^ 1) * K1_A_PLANE;
            float* Ar = sm + 2560 + (buf ^ 1) * K1_A_PLANE;
            float* Bb = sm + 5120 + (buf ^ 1) * K1_B_PLANE;
            float* Br = sm + 10240 + (buf ^ 1) * K1_B_PLANE;
            {
                int r = tid >> 2, kk = (tid & 3) * 4;
                float4 v = pa;
                float4 bg;
                bg.x = to_tf32(v.x); bg.y = to_tf32(v.y); bg.z = to_tf32(v.z); bg.w = to_tf32(v.w);
                *(float4*)(Ab + r * K1S + kk) = bg;
                if (RES) {
                    float4 rs;
                    rs.x = v.x - bg.x; rs.y = v.y - bg.y; rs.z = v.z - bg.z; rs.w = v.w - bg.w;
                    *(float4*)(Ar + r * K1S + kk) = rs;
                }
            }
            #pragma unroll
            for (int i = 0; i < 2; i++) {
                int f = tid + i * 256;
                int r = f >> 2, kk = (f & 3) * 4;
                float4 v = pbv[i];
                float4 bg;
                bg.x = to_tf32(v.x); bg.y = to_tf32(v.y); bg.z = to_tf32(v.z); bg.w = to_tf32(v.w);
                *(float4*)(Bb + r * K1S + kk) = bg;
                if (RES) {
                    float4 rs;
                    rs.x = v.x - bg.x; rs.y = v.y - bg.y; rs.z = v.z - bg.z; rs.w = v.w - bg.w;
                    *(float4*)(Br + r * K1S + kk) = rs;
                }
            }
            __syncthreads();
            buf ^= 1;
        }
    }

    // epilogue: bias + tanh
    const float* biasp = bias + cl;
    #pragma unroll
    for (int mt = 0; mt < 2; mt++) {
        int row = rowBase + warp_m * 32 + mt * 16 + g;
        #pragma unroll
        for (int nt = 0; nt < 4; nt++) {
            int cb = warp_n * 32 + nt * 8 + 2 * tig;
            float b0 = biasp[cb], b1 = biasp[cb + 1];
            int col = outOff + cl + cb;
            float2 p0, p1;
            p0.x = tanhf(acc[mt][nt][0] + b0);
            p0.y = tanhf(acc[mt][nt][1] + b1);
            p1.x = tanhf(acc[mt][nt][2] + b0);
            p1.y = tanhf(acc[mt][nt][3] + b1);
            *(float2*)&g_base[(size_t)row * (2 * DD) + col] = p0;
            *(float2*)&g_base[(size_t)(row + 8) * (2 * DD) + col] = p1;
        }
    }
}

// ============================================================================
// K2a: episodic priority + argmax + gate dots + scalar gates (k1-independent).
// ============================================================================
__global__ __launch_bounds__(256) void k2a_select(
    const float* __restrict__ ep_vals,
    const float* __restrict__ ep_str,  const float* __restrict__ ep_hits,
    const float* __restrict__ ep_age,
    const float* __restrict__ signal,  const float* __restrict__ hidden,
    const float* __restrict__ branch,  const float* __restrict__ entropy,
    const float* __restrict__ delay,
    const float* __restrict__ fgW, const float* __restrict__ fgb,
    const float* __restrict__ pgW, const float* __restrict__ pgb,
    const float* __restrict__ cgW, const float* __restrict__ cgb)
{
    const int b = blockIdx.x;
    const int tid = threadIdx.x;
    const int lane = tid & 31, w = tid >> 5;

    __shared__ float pr[MM];
    __shared__ float dots[3];
    __shared__ int   s_src;
    __shared__ float s_conf;

    #pragma unroll
    for (int mi = 0; mi < 4; mi++) {
        int m = w * 4 + mi;
        const float* row = ep_vals + ((size_t)b * MM + m) * DD;
        float ss = 0.f;
        #pragma unroll
        for (int j = 0; j < 4; j++) {
            float4 v = *(const float4*)(row + lane * 4 + j * 128);
            ss += v.x * v.x + v.y * v.y + v.z * v.z + v.w * v.w;
        }
        ss = wred(ss);
        if (lane == 0) {
            float epn = sqrtf(ss) * 0.0441941738f;   // /sqrt(512)
            pr[m] = 0.45f * ep_str[b * MM + m]
                  + 0.3f  * (ep_hits[b * MM + m] * (1.f / 6.f))
                  + 0.15f * (1.f - ep_age[b * MM + m])
                  + 0.1f  * clip01(epn);
        }
    }
    __syncthreads();

    if (w == 0) {
        float v = pr[lane]; int idx = lane;
        #pragma unroll
        for (int o = 16; o; o >>= 1) {
            float ov = __shfl_down_sync(0xffffffffu, v, o);
            int   oi = __shfl_down_sync(0xffffffffu, idx, o);
            if (ov > v || (ov == v && oi < idx)) { v = ov; idx = oi; }
        }
        if (lane == 0) { s_src = idx; s_conf = v; }
    }
    if (w >= 1 && w <= 3) {
        const float* Wg = (w == 1) ? fgW : (w == 2) ? pgW : cgW;
        float acc = 0.f;
        for (int i = lane; i < 2 * DD + 3; i += 32) {
            float r = (i < DD) ? signal[(size_t)b * DD + i]
                    : (i < 2 * DD) ? hidden[(size_t)b * DD + i - DD]
                    : branch[(size_t)b * 3 + (i - 2 * DD)];
            acc += r * Wg[i];
        }
        acc = wred(acc);
        if (lane == 0) dots[w - 1] = acc;
    }
    __syncthreads();

    if (tid == 0) {
        const float focus   = sigmoidf_(dots[0] + fgb[0]);
        const float pers    = sigmoidf_(dots[1] + pgb[0]);
        const float cons    = sigmoidf_(dots[2] + cgb[0] + 2.2f * (s_conf - 0.5f));
        const float compact = sigmoidf_((0.72f - entropy[b]) * 5.5f);
        const float kf      = clip01(0.45f * focus + 0.3f * compact + 0.25f * delay[b]);
        g_kf[b] = kf; g_cp[b] = compact; g_pers[b] = pers;
        g_cons[b] = cons; g_src[b] = s_src;
    }
}

// ============================================================================
// K2c: candidate_value only (needs val half of g_base + K2a). Side stream.
// ============================================================================
__global__ __launch_bounds__(256) void k2c_val(const float* __restrict__ ep_vals)
{
    const int b = blockIdx.x;
    const int tid = threadIdx.x;
    const float c = g_cons[b];
    const int src = g_src[b];
    const float* bv = g_base + (size_t)b * (2 * DD) + DD;
    const float* sv = ep_vals + ((size_t)b * MM + src) * DD;
    const float a = 1.f - 0.35f * c, s = 0.35f * c;
    #pragma unroll
    for (int o = 0; o < 2; o++) {
        int d = tid + o * 256;
        g_cv[(size_t)b * DD + d] = tanhf(a * bv[d] + s * sv[d]);
    }
}

// ============================================================================
// K3: candidate-key prologue + keys stream (read-once, write-through)
//     + all decisions + target key blend. Needs only k1_key + k2a.
// ============================================================================
__global__ __launch_bounds__(256) void k3_keys(
    const float* __restrict__ qk, const float* __restrict__ delay,
    const float* __restrict__ sal,
    const float* __restrict__ skeys, const float* __restrict__ ep_keys,
    const float* __restrict__ str_g, const float* __restrict__ age_g,
    const float* __restrict__ usg_g,
    float* __restrict__ out_hits, float* __restrict__ out_keys,
    float* __restrict__ out_str,  float* __restrict__ out_age,
    float* __restrict__ out_usg)
{
    __shared__ __align__(16) float sq[DD], sck[DD];
    __shared__ float scores[NN], sim[NN], repl[NN];
    __shared__ float sstr[NN], sage[NN], susg[NN];
    __shared__ float red[9];
    __shared__ float bc[6];
    __shared__ int   bci[3];

    const int b = blockIdx.x;
    const int tid = threadIdx.x;
    const int lane = tid & 31, w = tid >> 5;

    // ---- prologue: build candidate_key in sck ----
    {
        const float cns = g_cons[b];
        const int   es  = g_src[b];
        const float* bkp = g_base + (size_t)b * (2 * DD);
        const float* skp = ep_keys + ((size_t)b * MM + es) * DD;
        sq[tid]       = qk[(size_t)b * DD + tid];
        sq[tid + 256] = qk[(size_t)b * DD + tid + 256];
        float m0 = (1.f - cns) * bkp[tid]       + cns * skp[tid];
        float m1 = (1.f - cns) * bkp[tid + 256] + cns * skp[tid + 256];
        sck[tid] = m0; sck[tid + 256] = m1;
        float ssq = wred(m0 * m0 + m1 * m1);
        if (lane == 0) red[w] = ssq;
        if (tid < NN) {
            float s = str_g[b * NN + tid], a = age_g[b * NN + tid], u = usg_g[b * NN + tid];
            sstr[tid] = s; sage[tid] = a; susg[tid] = u;
            repl[tid] = 1.3f * a + (1.f - s) + 0.9f * (1.f - u);
        }
        __syncthreads();
        if (tid == 0) {
            float t = 0.f;
            #pragma unroll
            for (int i = 0; i < 8; i++) t += red[i];
            red[8] = 1.f / fmaxf(sqrtf(t), 1e-6f);
        }
        __syncthreads();
        const float invn = red[8];
        sck[tid]       *= invn;
        sck[tid + 256] *= invn;
        __syncthreads();
    }

    float4 qv[4], cvv[4];
    #pragma unroll
    for (int j = 0; j < 4; j++) {
        qv[j]  = ((const float4*)sq)[lane + j * 32];
        cvv[j] = ((const float4*)sck)[lane + j * 32];
    }

    const float4* kin = (const float4*)(skeys + (size_t)b * NN * DD);
    float4* kout = (float4*)(out_keys + (size_t)b * NN * DD);
    const float dg = delay[b], sg = sal[b];

    #pragma unroll
    for (int p = 0; p < 4; p++) {
        const int n0 = w * 8 + p * 2, n1 = n0 + 1;
        float4 r0[4], r1[4];
        #pragma unroll
        for (int j = 0; j < 4; j++) r0[j] = kin[n0 * 128 + lane + j * 32];
        #pragma unroll
        for (int j = 0; j < 4; j++) r1[j] = kin[n1 * 128 + lane + j * 32];
        #pragma unroll
        for (int j = 0; j < 4; j++) kout[n0 * 128 + lane + j * 32] = r0[j];
        #pragma unroll
        for (int j = 0; j < 4; j++) kout[n1 * 128 + lane + j * 32] = r1[j];

        float ss0 = 0.f, dq0 = 0.f, dc0 = 0.f, ss1 = 0.f, dq1 = 0.f, dc1 = 0.f;
        #pragma unroll
        for (int j = 0; j < 4; j++) {
            ss0 += r0[j].x * r0[j].x + r0[j].y * r0[j].y + r0[j].z * r0[j].z + r0[j].w * r0[j].w;
            dq0 += r0[j].x * qv[j].x + r0[j].y * qv[j].y + r0[j].z * qv[j].z + r0[j].w * qv[j].w;
            dc0 += r0[j].x * cvv[j].x + r0[j].y * cvv[j].y + r0[j].z * cvv[j].z + r0[j].w * cvv[j].w;
            ss1 += r1[j].x * r1[j].x + r1[j].y * r1[j].y + r1[j].z * r1[j].z + r1[j].w * r1[j].w;
            dq1 += r1[j].x * qv[j].x + r1[j].y * qv[j].y + r1[j].z * qv[j].z + r1[j].w * qv[j].w;
            dc1 += r1[j].x * cvv[j].x + r1[j].y * cvv[j].y + r1[j].z * cvv[j].z + r1[j].w * cvv[j].w;
        }
        ss0 = wred(ss0); dq0 = wred(dq0); dc0 = wred(dc0);
        ss1 = wred(ss1); dq1 = wred(dq1); dc1 = wred(dc1);
        if (lane == 0) {
            float inv0 = 1.f / fmaxf(sqrtf(ss0), 1e-6f);
            float inv1 = 1.f / fmaxf(sqrtf(ss1), 1e-6f);
            sim[n0] = dc0 * inv0;
            sim[n1] = dc1 * inv1;
            float pr0 = 2.8f * sstr[n0] + 0.9f * susg[n0] + 0.6f * (1.f - sage[n0]);
            float pr1 = 2.8f * sstr[n1] + 0.9f * susg[n1] + 0.6f * (1.f - sage[n1]);
            scores[n0] = 0.65f * dq0 * inv0 + 0.22f * pr0 + 0.08f * dg * sage[n0] + 0.05f * sg * sstr[n0];
            scores[n1] = 0.65f * dq1 * inv1 + 0.22f * pr1 + 0.08f * dg * sage[n1] + 0.05f * sg * sstr[n1];
        }
    }
    __syncthreads();

    if (tid == 0) {
        int i1 = 0;
        for (int n = 1; n < NN; n++) if (scores[n] > scores[i1]) i1 = n;
        int i2 = -1;
        for (int n = 0; n < NN; n++) {
            if (n == i1) continue;
            if (i2 < 0 || scores[n] > scores[i2]) i2 = n;
        }
        float w1 = 1.f / (1.f + expf((scores[i2] - scores[i1]) * 2.f)); // TEMP=0.5
        float w2 = 1.f - w1;
        int mi = 0;
        for (int n = 1; n < NN; n++) if (sim[n] > sim[mi]) mi = n;
        int ri = 0;
        for (int n = 1; n < NN; n++) if (repl[n] > repl[ri]) ri = n;
        bool um = sim[mi] > 0.81f;
        int target = um ? mi : ri;
        float kf = g_kf[b], cp = g_cp[b], p = g_pers[b];
        float ow = (0.1f + 0.8f * kf) * (0.55f + 0.45f * cp);
        float kmix = um ? (0.18f + 0.24f * p) : (0.78f + 0.1f * p);
        float vmix = um ? (0.34f + 0.22f * p) : (0.82f + 0.1f * p);
        bc[0] = w1; bc[1] = w2; bc[2] = ow * kmix; bc[3] = ow; bc[4] = kf; bc[5] = p;
        bci[0] = i1; bci[1] = i2; bci[2] = target;
        g_i1[b] = i1; g_i2[b] = i2; g_tg[b] = target;
        g_w1[b] = w1; g_w2[b] = w2; g_ovm[b] = ow * vmix;
    }
    __syncthreads();

    const float w1 = bc[0], w2 = bc[1], owk = bc[2], ow = bc[3], kf = bc[4], p = bc[5];
    const int i1 = bci[0], i2 = bci[1], target = bci[2];

    if (tid < NN) {
        int n = tid;
        out_hits[(size_t)b * NN + n] = (n == i1) ? w1 : (n == i2) ? w2 : 0.f;
        float own = (n == target) ? ow : 0.f;
        out_str[(size_t)b * NN + n] = clip01(sstr[n] * 0.97f + own * (0.55f + 0.2f * kf + 0.15f * p));
        out_usg[(size_t)b * NN + n] = clip01(susg[n] * 0.96f + own * (0.6f + 0.4f * dg));
        out_age[(size_t)b * NN + n] = clip01((sage[n] + 0.02f) * (1.f - 0.85f * own));
    }

    if (tid >= 128) {
        int t = tid - 128;
        float4 v = kin[target * 128 + t];       // L2-hot
        float4 c = ((const float4*)sck)[t];
        v.x += owk * (c.x - v.x);
        v.y += owk * (c.y - v.y);
        v.z += owk * (c.z - v.z);
        v.w += owk * (c.w - v.w);
        kout[target * 128 + t] = v;
    }
}

// ============================================================================
// K4a: pure values copy (no dependencies — side stream). Deep MLP (8 in flight).
// ============================================================================
__global__ __launch_bounds__(256) void k4a_copy(
    const float* __restrict__ svals, float* __restrict__ out_vals)
{
    const int b = blockIdx.x;
    const int tid = threadIdx.x;
    const float4* src = (const float4*)(svals + (size_t)b * NN * DD);
    float4* dst = (float4*)(out_vals + (size_t)b * NN * DD);
    #pragma unroll
    for (int o = 0; o < 4; o++) {
        int i = tid + o * 2048;
        float4 v[8];
        #pragma unroll
        for (int j = 0; j < 8; j++) v[j] = src[i + j * 256];
        #pragma unroll
        for (int j = 0; j < 8; j++) dst[i + j * 256] = v[j];
    }
}

// ============================================================================
// K4b: target value-row blend + read_out (after K3, K4a, K2c).
// ============================================================================
__global__ __launch_bounds__(256) void k4b_fixup(
    const float* __restrict__ svals,
    float* __restrict__ out_vals, float* __restrict__ out_read)
{
    const int b = blockIdx.x;
    const int tid = threadIdx.x;
    const float4* src = (const float4*)(svals + (size_t)b * NN * DD);
    float4* dst = (float4*)(out_vals + (size_t)b * NN * DD);

    if (tid < 128) {
        const int target = g_tg[b];
        const float ovm = g_ovm[b];
        float4 v = src[target * 128 + tid];
        float4 c = ((const float4*)(g_cv + (size_t)b * DD))[tid];
        v.x += ovm * (c.x - v.x);
        v.y += ovm * (c.y - v.y);
        v.z += ovm * (c.z - v.z);
        v.w += ovm * (c.w - v.w);
        dst[target * 128 + tid] = v;
    } else {
        const int t = tid - 128;
        const int i1 = g_i1[b], i2 = g_i2[b];
        const float w1 = g_w1[b], w2 = g_w2[b];
        float4 a = src[i1 * 128 + t];
        float4 c2 = src[i2 * 128 + t];
        float4 o;
        o.x = w1 * a.x + w2 * c2.x;
        o.y = w1 * a.y + w2 * c2.y;
        o.z = w1 * a.z + w2 * c2.z;
        o.w = w1 * a.w + w2 * c2.w;
        ((float4*)(out_read + (size_t)b * DD))[t] = o;
    }
}

// ============================================================================
extern "C" void kernel_launch(void* const* d_in, const int* in_sizes, int n_in,
                              void* d_out, int out_size)
{
    const float* query_key   = (const float*)d_in[0];
    const float* delay_gate  = (const float*)d_in[1];
    const float* sal_gate    = (const float*)d_in[2];
    const float* short_keys  = (const float*)d_in[3];
    const float* short_vals  = (const float*)d_in[4];
    const float* short_str   = (const float*)d_in[5];
    const float* short_age   = (const float*)d_in[6];
    const float* short_usg   = (const float*)d_in[7];
    const float* signal      = (const float*)d_in[8];
    const float* hidden      = (const float*)d_in[9];
    const float* branch      = (const float*)d_in[10];
    const float* entropy     = (const float*)d_in[11];
    const float* ep_keys     = (const float*)d_in[12];
    const float* ep_vals     = (const float*)d_in[13];
    const float* ep_str      = (const float*)d_in[14];
    const float* ep_hits     = (const float*)d_in[15];
    const float* ep_age      = (const float*)d_in[16];
    const float* key_W       = (const float*)d_in[17];
    const float* key_b       = (const float*)d_in[18];
    const float* val_W       = (const float*)d_in[19];
    const float* val_b       = (const float*)d_in[20];
    const float* fg_W        = (const float*)d_in[21];
    const float* fg_b        = (const float*)d_in[22];
    const float* pg_W        = (const float*)d_in[23];
    const float* pg_b        = (const float*)d_in[24];
    const float* cg_W        = (const float*)d_in[25];
    const float* cg_b        = (const float*)d_in[26];

    float* out = (float*)d_out;
    float* o_read = out;                              // B*D
    float* o_hits = o_read + (size_t)BB * DD;         // B*N
    float* o_keys = o_hits + (size_t)BB * NN;         // B*N*D
    float* o_vals = o_keys + (size_t)BB * NN * DD;    // B*N*D
    float* o_str  = o_vals + (size_t)BB * NN * DD;    // B*N
    float* o_age  = o_str  + (size_t)BB * NN;         // B*N
    float* o_usg  = o_age  + (size_t)BB * NN;         // B*N

    const int k1_smem = 15360 * (int)sizeof(float);   // 61440 B

    static bool init_done = false;
    static cudaStream_t sA, sB, sC;
    static cudaEvent_t e0, eA, eB, eC;
    if (!init_done) {
        cudaStreamCreateWithFlags(&sA, cudaStreamNonBlocking);
        cudaStreamCreateWithFlags(&sB, cudaStreamNonBlocking);
        cudaStreamCreateWithFlags(&sC, cudaStreamNonBlocking);
        cudaEventCreateWithFlags(&e0, cudaEventDisableTiming);
        cudaEventCreateWithFlags(&eA, cudaEventDisableTiming);
        cudaEventCreateWithFlags(&eB, cudaEventDisableTiming);
        cudaEventCreateWithFlags(&eC, cudaEventDisableTiming);
        cudaFuncSetAttribute(k1_gemm<true>,
                             cudaFuncAttributeMaxDynamicSharedMemorySize, k1_smem);
        cudaFuncSetAttribute(k1_gemm<false>,
                             cudaFuncAttributeMaxDynamicSharedMemorySize, k1_smem);
        init_done = true;
    }

    // fork
    cudaEventRecord(e0, 0);
    cudaStreamWaitEvent(sA, e0, 0);
    cudaStreamWaitEvent(sB, e0, 0);
    cudaStreamWaitEvent(sC, e0, 0);

    // critical path: key-half GEMM first (3-term split, feeds all decisions).
    // 128 blocks -> ~128 SMs; k2a/copy blocks co-reside & backfill.
    dim3 gk(DD / 128, BB / 64);   // (4, 32) = 128 blocks
    k1_gemm<true><<<gk, 256, k1_smem>>>(signal, hidden, key_W, key_b, 0);

    // k2a early (k3 needs it), co-resident with the GEMM (tiny smem)
    k2a_select<<<BB, 256, 0, sB>>>(ep_vals, ep_str, ep_hits, ep_age,
                                   signal, hidden, branch, entropy, delay_gate,
                                   fg_W, fg_b, pg_W, pg_b, cg_W, cg_b);
    cudaEventRecord(eB, sB);

    // values copy streams DRAM while the tensor pipes grind the GEMM
    k4a_copy<<<BB, 256, 0, sA>>>(short_vals, o_vals);
    cudaEventRecord(eA, sA);

    // value-half GEMM (single tf32) — only needed by k2c/k4b at the end
    k1_gemm<false><<<gk, 256, k1_smem, sC>>>(signal, hidden, val_W, val_b, DD);

    // candidate_value on sC (needs k1_val [same stream] + k2a)
    cudaStreamWaitEvent(sC, eB, 0);
    k2c_val<<<BB, 256, 0, sC>>>(ep_vals);
    cudaEventRecord(eC, sC);

    // main: k3 needs k1_key (same stream) + k2a
    cudaStreamWaitEvent(0, eB, 0);
    k3_keys<<<BB, 256>>>(query_key, delay_gate, sal_gate, short_keys, ep_keys,
                         short_str, short_age, short_usg,
                         o_hits, o_keys, o_str, o_age, o_usg);

    // join copy + candidate_value, then fix up target row + read_out
    cudaStreamWaitEvent(0, eA, 0);
    cudaStreamWaitEvent(0, eC, 0);
    k4b_fixup<<<BB, 256>>>(short_vals, o_vals, o_read);
}

// round 15
// speedup vs baseline: 1.0817x; 1.0095x over previous
#include <cuda_runtime.h>
#include <cuda_bf16.h>
#include <math.h>
#include <stdint.h>

// Problem constants
#define BB 2048
#define DD 512
#define NN 64
#define MM 32
// DECAY=0.97 AGE_INC=0.02 TEMP=0.5

// ---------------- scratch (static device globals; no allocation) -------------
// raw GEMM partial sums: part p, batch b, col j (0..511 key, 512..1023 value)
__device__ float g_part[2 * BB * 2 * DD];
__device__ float g_cv[BB * DD];         // candidate_value (tanh'd)
__device__ float g_kf[BB];              // key_focus
__device__ float g_cp[BB];              // compactness
__device__ float g_pers[BB];            // persistence
__device__ float g_cons[BB];            // consolidation
__device__ int   g_src[BB];             // episodic argmax index
__device__ int   g_i1[BB], g_i2[BB], g_tg[BB];
__device__ float g_w1[BB], g_w2[BB], g_ovm[BB];

__device__ __forceinline__ float wred(float v) {
    #pragma unroll
    for (int o = 16; o; o >>= 1) v += __shfl_down_sync(0xffffffffu, v, o);
    return v;
}
__device__ __forceinline__ float sigmoidf_(float x) { return 1.f / (1.f + expf(-x)); }
__device__ __forceinline__ float clip01(float x) { return fminf(fmaxf(x, 0.f), 1.f); }

__device__ __forceinline__ float to_tf32(float x) {
    uint32_t u;
    asm("cvt.rna.tf32.f32 %0, %1;" : "=r"(u) : "f"(x));
    return __uint_as_float(u);
}
__device__ __forceinline__ void mma_tf32(float c[4],
    uint32_t a0, uint32_t a1, uint32_t a2, uint32_t a3,
    uint32_t b0, uint32_t b1)
{
    asm volatile(
        "mma.sync.aligned.m16n8k8.row.col.f32.tf32.tf32.f32 "
        "{%0,%1,%2,%3}, {%4,%5,%6,%7}, {%8,%9}, {%0,%1,%2,%3};"
        : "+f"(c[0]), "+f"(c[1]), "+f"(c[2]), "+f"(c[3])
        : "r"(a0), "r"(a1), "r"(a2), "r"(a3), "r"(b0), "r"(b1));
}

// ============================================================================
// K1: K-split GEMM partials. blockIdx.z = part (0: signal x W[:,0:512],
// 1: hidden x W[:,512:1024]). Block tile 64M x 128N x 16K, 32 kt-iterations.
// Writes RAW partial sums to g_part[part] (bias+tanh folded into consumers).
// RES=true : 3-term TF32 split (key half). RES=false: single TF32 (value half).
// ============================================================================
#define K1S 20                   // padded row stride (floats)
#define K1_A_PLANE (64 * K1S)    // 1280 floats
#define K1_B_PLANE (128 * K1S)   // 2560 floats

template<bool RES>
__global__ __launch_bounds__(256) void k1_gemm(
    const float* __restrict__ signal, const float* __restrict__ hidden,
    const float* __restrict__ W, int outOff)
{
    extern __shared__ __align__(16) float sm[];
    // RES=true : Ab[2]@0, Ar[2]@2560, Bb[2]@5120, Br[2]@10240  (15360 fl, 60KB)
    // RES=false: Ab[2]@0,            Bb[2]@2560               (7680 fl, 30KB)
    constexpr int AR_OFF = RES ? 2560 : 0;
    constexpr int BB_OFF = RES ? 5120 : 2560;
    constexpr int BR_OFF = RES ? 10240 : 0;

    const int tid = threadIdx.x;
    const int lane = tid & 31, wid = tid >> 5;
    const int g = lane >> 2, tig = lane & 3;
    const int warp_m = wid & 1, warp_n = wid >> 1;

    const int part = blockIdx.z;
    const float* __restrict__ A = part ? hidden : signal;
    const int wOff = part * DD;

    const int rowBase = blockIdx.y * 64;
    const int cl = blockIdx.x * 128;     // local column within this half

    float acc[2][4][4];
    #pragma unroll
    for (int mt = 0; mt < 2; mt++)
        #pragma unroll
        for (int nt = 0; nt < 4; nt++)
            #pragma unroll
            for (int i = 0; i < 4; i++) acc[mt][nt][i] = 0.f;

    float4 pa, pbv[2];

    // prefetch kt=0
    {
        int r = tid >> 2, kk = (tid & 3) * 4;
        pa = *(const float4*)(A + (size_t)(rowBase + r) * DD + kk);
        #pragma unroll
        for (int i = 0; i < 2; i++) {
            int f = tid + i * 256;
            int rb = f >> 2, kb = (f & 3) * 4;
            pbv[i] = *(const float4*)(W + (size_t)(cl + rb) * (2 * DD) + wOff + kb);
        }
    }
    // stage buf 0
    {
        float* Ab = sm;           float* Ar = sm + AR_OFF;
        float* Bb = sm + BB_OFF;  float* Br = sm + BR_OFF;
        {
            int r = tid >> 2, kk = (tid & 3) * 4;
            float4 v = pa;
            float4 bg;
            bg.x = to_tf32(v.x); bg.y = to_tf32(v.y); bg.z = to_tf32(v.z); bg.w = to_tf32(v.w);
            *(float4*)(Ab + r * K1S + kk) = bg;
            if (RES) {
                float4 rs;
                rs.x = v.x - bg.x; rs.y = v.y - bg.y; rs.z = v.z - bg.z; rs.w = v.w - bg.w;
                *(float4*)(Ar + r * K1S + kk) = rs;
            }
        }
        #pragma unroll
        for (int i = 0; i < 2; i++) {
            int f = tid + i * 256;
            int r = f >> 2, kk = (f & 3) * 4;
            float4 v = pbv[i];
            float4 bg;
            bg.x = to_tf32(v.x); bg.y = to_tf32(v.y); bg.z = to_tf32(v.z); bg.w = to_tf32(v.w);
            *(float4*)(Bb + r * K1S + kk) = bg;
            if (RES) {
                float4 rs;
                rs.x = v.x - bg.x; rs.y = v.y - bg.y; rs.z = v.z - bg.z; rs.w = v.w - bg.w;
                *(float4*)(Br + r * K1S + kk) = rs;
            }
        }
    }
    __syncthreads();

    int buf = 0;
    for (int kt = 0; kt < DD; kt += 16) {        // 32 iterations (K-split)
        const bool has = (kt + 16) < DD;
        if (has) {
            const int ktn = kt + 16;
            {
                int r = tid >> 2, kk = (tid & 3) * 4;
                pa = *(const float4*)(A + (size_t)(rowBase + r) * DD + ktn + kk);
            }
            #pragma unroll
            for (int i = 0; i < 2; i++) {
                int f = tid + i * 256;
                int r = f >> 2, kk = (f & 3) * 4;
                pbv[i] = *(const float4*)(W + (size_t)(cl + r) * (2 * DD) + wOff + ktn + kk);
            }
        }

        // compute from buf
        {
            const float* Abf = sm + buf * K1_A_PLANE;
            const float* Arf = sm + AR_OFF + buf * K1_A_PLANE;
            const float* Bbf = sm + BB_OFF + buf * K1_B_PLANE;
            const float* Brf = sm + BR_OFF + buf * K1_B_PLANE;
            #pragma unroll
            for (int ks = 0; ks < 16; ks += 8) {
                const int c0 = ks + tig;
                uint32_t ab[2][4], ar[2][4], bbf[4][2], brf[4][2];
                #pragma unroll
                for (int mt = 0; mt < 2; mt++) {
                    int r0 = warp_m * 32 + mt * 16 + g;
                    ab[mt][0] = __float_as_uint(Abf[r0 * K1S + c0]);
                    ab[mt][1] = __float_as_uint(Abf[(r0 + 8) * K1S + c0]);
                    ab[mt][2] = __float_as_uint(Abf[r0 * K1S + c0 + 4]);
                    ab[mt][3] = __float_as_uint(Abf[(r0 + 8) * K1S + c0 + 4]);
                    if (RES) {
                        ar[mt][0] = __float_as_uint(Arf[r0 * K1S + c0]);
                        ar[mt][1] = __float_as_uint(Arf[(r0 + 8) * K1S + c0]);
                        ar[mt][2] = __float_as_uint(Arf[r0 * K1S + c0 + 4]);
                        ar[mt][3] = __float_as_uint(Arf[(r0 + 8) * K1S + c0 + 4]);
                    }
                }
                #pragma unroll
                for (int nt = 0; nt < 4; nt++) {
                    int n0 = warp_n * 32 + nt * 8 + g;
                    bbf[nt][0] = __float_as_uint(Bbf[n0 * K1S + c0]);
                    bbf[nt][1] = __float_as_uint(Bbf[n0 * K1S + c0 + 4]);
                    if (RES) {
                        brf[nt][0] = __float_as_uint(Brf[n0 * K1S + c0]);
                        brf[nt][1] = __float_as_uint(Brf[n0 * K1S + c0 + 4]);
                    }
                }
                #pragma unroll
                for (int mt = 0; mt < 2; mt++)
                    #pragma unroll
                    for (int nt = 0; nt < 4; nt++) {
                        mma_tf32(acc[mt][nt], ab[mt][0], ab[mt][1], ab[mt][2], ab[mt][3],
                                 bbf[nt][0], bbf[nt][1]);
                        if (RES) {
                            mma_tf32(acc[mt][nt], ab[mt][0], ab[mt][1], ab[mt][2], ab[mt][3],
                                     brf[nt][0], brf[nt][1]);
                            mma_tf32(acc[mt][nt], ar[mt][0], ar[mt][1], ar[mt][2], ar[mt][3],
                                     bbf[nt][0], bbf[nt][1]);
                        }
                    }
            }
        }

        if (has) {
            float* Ab = sm + (buf ^ 1) * K1_A_PLANE;
            float* Ar = sm + AR_OFF + (buf ^ 1) * K1_A_PLANE;
            float* Bb = sm + BB_OFF + (buf ^ 1) * K1_B_PLANE;
            float* Br = sm + BR_OFF + (buf ^ 1) * K1_B_PLANE;
            {
                int r = tid >> 2, kk = (tid & 3) * 4;
                float4 v = pa;
                float4 bg;
                bg.x = to_tf32(v.x); bg.y = to_tf32(v.y); bg.z = to_tf32(v.z); bg.w = to_tf32(v.w);
                *(float4*)(Ab + r * K1S + kk) = bg;
                if (RES) {
                    float4 rs;
                    rs.x = v.x - bg.x; rs.y = v.y - bg.y; rs.z = v.z - bg.z; rs.w = v.w - bg.w;
                    *(float4*)(Ar + r * K1S + kk) = rs;
                }
            }
            #pragma unroll
            for (int i = 0; i < 2; i++) {
                int f = tid + i * 256;
                int r = f >> 2, kk = (f & 3) * 4;
                float4 v = pbv[i];
                float4 bg;
                bg.x = to_tf32(v.x); bg.y = to_tf32(v.y); bg.z = to_tf32(v.z); bg.w = to_tf32(v.w);
                *(float4*)(Bb + r * K1S + kk) = bg;
                if (RES) {
                    float4 rs;
                    rs.x = v.x - bg.x; rs.y = v.y - bg.y; rs.z = v.z - bg.z; rs.w = v.w - bg.w;
                    *(float4*)(Br + r * K1S + kk) = rs;
                }
            }
            __syncthreads();
            buf ^= 1;
        }
    }

    // epilogue: RAW partial sums (bias+tanh in consumers)
    float* dst = g_part + (size_t)part * (BB * 2 * DD);
    #pragma unroll
    for (int mt = 0; mt < 2; mt++) {
        int row = rowBase + warp_m * 32 + mt * 16 + g;
        #pragma unroll
        for (int nt = 0; nt < 4; nt++) {
            int cb = warp_n * 32 + nt * 8 + 2 * tig;
            int col = outOff + cl + cb;
            float2 p0, p1;
            p0.x = acc[mt][nt][0]; p0.y = acc[mt][nt][1];
            p1.x = acc[mt][nt][2]; p1.y = acc[mt][nt][3];
            *(float2*)&dst[(size_t)row * (2 * DD) + col] = p0;
            *(float2*)&dst[(size_t)(row + 8) * (2 * DD) + col] = p1;
        }
    }
}

// ============================================================================
// K2a: episodic priority + argmax + gate dots + scalar gates (k1-independent).
// ============================================================================
__global__ __launch_bounds__(256) void k2a_select(
    const float* __restrict__ ep_vals,
    const float* __restrict__ ep_str,  const float* __restrict__ ep_hits,
    const float* __restrict__ ep_age,
    const float* __restrict__ signal,  const float* __restrict__ hidden,
    const float* __restrict__ branch,  const float* __restrict__ entropy,
    const float* __restrict__ delay,
    const float* __restrict__ fgW, const float* __restrict__ fgb,
    const float* __restrict__ pgW, const float* __restrict__ pgb,
    const float* __restrict__ cgW, const float* __restrict__ cgb)
{
    const int b = blockIdx.x;
    const int tid = threadIdx.x;
    const int lane = tid & 31, w = tid >> 5;

    __shared__ float pr[MM];
    __shared__ float dots[3];
    __shared__ int   s_src;
    __shared__ float s_conf;

    #pragma unroll
    for (int mi = 0; mi < 4; mi++) {
        int m = w * 4 + mi;
        const float* row = ep_vals + ((size_t)b * MM + m) * DD;
        float ss = 0.f;
        #pragma unroll
        for (int j = 0; j < 4; j++) {
            float4 v = *(const float4*)(row + lane * 4 + j * 128);
            ss += v.x * v.x + v.y * v.y + v.z * v.z + v.w * v.w;
        }
        ss = wred(ss);
        if (lane == 0) {
            float epn = sqrtf(ss) * 0.0441941738f;   // /sqrt(512)
            pr[m] = 0.45f * ep_str[b * MM + m]
                  + 0.3f  * (ep_hits[b * MM + m] * (1.f / 6.f))
                  + 0.15f * (1.f - ep_age[b * MM + m])
                  + 0.1f  * clip01(epn);
        }
    }
    __syncthreads();

    if (w == 0) {
        float v = pr[lane]; int idx = lane;
        #pragma unroll
        for (int o = 16; o; o >>= 1) {
            float ov = __shfl_down_sync(0xffffffffu, v, o);
            int   oi = __shfl_down_sync(0xffffffffu, idx, o);
            if (ov > v || (ov == v && oi < idx)) { v = ov; idx = oi; }
        }
        if (lane == 0) { s_src = idx; s_conf = v; }
    }
    if (w >= 1 && w <= 3) {
        const float* Wg = (w == 1) ? fgW : (w == 2) ? pgW : cgW;
        float acc = 0.f;
        for (int i = lane; i < 2 * DD + 3; i += 32) {
            float r = (i < DD) ? signal[(size_t)b * DD + i]
                    : (i < 2 * DD) ? hidden[(size_t)b * DD + i - DD]
                    : branch[(size_t)b * 3 + (i - 2 * DD)];
            acc += r * Wg[i];
        }
        acc = wred(acc);
        if (lane == 0) dots[w - 1] = acc;
    }
    __syncthreads();

    if (tid == 0) {
        const float focus   = sigmoidf_(dots[0] + fgb[0]);
        const float pers    = sigmoidf_(dots[1] + pgb[0]);
        const float cons    = sigmoidf_(dots[2] + cgb[0] + 2.2f * (s_conf - 0.5f));
        const float compact = sigmoidf_((0.72f - entropy[b]) * 5.5f);
        const float kf      = clip01(0.45f * focus + 0.3f * compact + 0.25f * delay[b]);
        g_kf[b] = kf; g_cp[b] = compact; g_pers[b] = pers;
        g_cons[b] = cons; g_src[b] = s_src;
    }
}

// ============================================================================
// K2c: candidate_value (folds val bias+tanh of partials). Needs k1_val + k2a.
// ============================================================================
__global__ __launch_bounds__(256) void k2c_val(
    const float* __restrict__ ep_vals, const float* __restrict__ valb)
{
    const int b = blockIdx.x;
    const int tid = threadIdx.x;
    const float c = g_cons[b];
    const int src = g_src[b];
    const float* P0 = g_part + (size_t)b * (2 * DD) + DD;
    const float* P1 = g_part + (size_t)(BB * 2 * DD) + (size_t)b * (2 * DD) + DD;
    const float* sv = ep_vals + ((size_t)b * MM + src) * DD;
    const float a = 1.f - 0.35f * c, s = 0.35f * c;
    #pragma unroll
    for (int o = 0; o < 2; o++) {
        int d = tid + o * 256;
        float bv = tanhf(P0[d] + P1[d] + valb[d]);
        g_cv[(size_t)b * DD + d] = tanhf(a * bv + s * sv[d]);
    }
}

// ============================================================================
// K3: candidate-key prologue (folds key bias+tanh of partials) + keys stream
//     + all decisions + target key blend. Needs only k1_key + k2a.
// ============================================================================
__global__ __launch_bounds__(256) void k3_keys(
    const float* __restrict__ qk, const float* __restrict__ delay,
    const float* __restrict__ sal,
    const float* __restrict__ skeys, const float* __restrict__ ep_keys,
    const float* __restrict__ keyb,
    const float* __restrict__ str_g, const float* __restrict__ age_g,
    const float* __restrict__ usg_g,
    float* __restrict__ out_hits, float* __restrict__ out_keys,
    float* __restrict__ out_str,  float* __restrict__ out_age,
    float* __restrict__ out_usg)
{
    __shared__ __align__(16) float sq[DD], sck[DD];
    __shared__ float scores[NN], sim[NN], repl[NN];
    __shared__ float sstr[NN], sage[NN], susg[NN];
    __shared__ float red[9];
    __shared__ float bc[6];
    __shared__ int   bci[3];

    const int b = blockIdx.x;
    const int tid = threadIdx.x;
    const int lane = tid & 31, w = tid >> 5;

    // ---- prologue: base_key = tanh(p0+p1+bias); candidate_key in sck ----
    {
        const float cns = g_cons[b];
        const int   es  = g_src[b];
        const float* P0 = g_part + (size_t)b * (2 * DD);
        const float* P1 = g_part + (size_t)(BB * 2 * DD) + (size_t)b * (2 * DD);
        const float* skp = ep_keys + ((size_t)b * MM + es) * DD;
        sq[tid]       = qk[(size_t)b * DD + tid];
        sq[tid + 256] = qk[(size_t)b * DD + tid + 256];
        float bk0 = tanhf(P0[tid]       + P1[tid]       + keyb[tid]);
        float bk1 = tanhf(P0[tid + 256] + P1[tid + 256] + keyb[tid + 256]);
        float m0 = (1.f - cns) * bk0 + cns * skp[tid];
        float m1 = (1.f - cns) * bk1 + cns * skp[tid + 256];
        sck[tid] = m0; sck[tid + 256] = m1;
        float ssq = wred(m0 * m0 + m1 * m1);
        if (lane == 0) red[w] = ssq;
        if (tid < NN) {
            float s = str_g[b * NN + tid], a = age_g[b * NN + tid], u = usg_g[b * NN + tid];
            sstr[tid] = s; sage[tid] = a; susg[tid] = u;
            repl[tid] = 1.3f * a + (1.f - s) + 0.9f * (1.f - u);
        }
        __syncthreads();
        if (tid == 0) {
            float t = 0.f;
            #pragma unroll
            for (int i = 0; i < 8; i++) t += red[i];
            red[8] = 1.f / fmaxf(sqrtf(t), 1e-6f);
        }
        __syncthreads();
        const float invn = red[8];
        sck[tid]       *= invn;
        sck[tid + 256] *= invn;
        __syncthreads();
    }

    float4 qv[4], cvv[4];
    #pragma unroll
    for (int j = 0; j < 4; j++) {
        qv[j]  = ((const float4*)sq)[lane + j * 32];
        cvv[j] = ((const float4*)sck)[lane + j * 32];
    }

    const float4* kin = (const float4*)(skeys + (size_t)b * NN * DD);
    float4* kout = (float4*)(out_keys + (size_t)b * NN * DD);
    const float dg = delay[b], sg = sal[b];

    #pragma unroll
    for (int p = 0; p < 4; p++) {
        const int n0 = w * 8 + p * 2, n1 = n0 + 1;
        float4 r0[4], r1[4];
        #pragma unroll
        for (int j = 0; j < 4; j++) r0[j] = kin[n0 * 128 + lane + j * 32];
        #pragma unroll
        for (int j = 0; j < 4; j++) r1[j] = kin[n1 * 128 + lane + j * 32];
        #pragma unroll
        for (int j = 0; j < 4; j++) kout[n0 * 128 + lane + j * 32] = r0[j];
        #pragma unroll
        for (int j = 0; j < 4; j++) kout[n1 * 128 + lane + j * 32] = r1[j];

        float ss0 = 0.f, dq0 = 0.f, dc0 = 0.f, ss1 = 0.f, dq1 = 0.f, dc1 = 0.f;
        #pragma unroll
        for (int j = 0; j < 4; j++) {
            ss0 += r0[j].x * r0[j].x + r0[j].y * r0[j].y + r0[j].z * r0[j].z + r0[j].w * r0[j].w;
            dq0 += r0[j].x * qv[j].x + r0[j].y * qv[j].y + r0[j].z * qv[j].z + r0[j].w * qv[j].w;
            dc0 += r0[j].x * cvv[j].x + r0[j].y * cvv[j].y + r0[j].z * cvv[j].z + r0[j].w * cvv[j].w;
            ss1 += r1[j].x * r1[j].x + r1[j].y * r1[j].y + r1[j].z * r1[j].z + r1[j].w * r1[j].w;
            dq1 += r1[j].x * qv[j].x + r1[j].y * qv[j].y + r1[j].z * qv[j].z + r1[j].w * qv[j].w;
            dc1 += r1[j].x * cvv[j].x + r1[j].y * cvv[j].y + r1[j].z * cvv[j].z + r1[j].w * cvv[j].w;
        }
        ss0 = wred(ss0); dq0 = wred(dq0); dc0 = wred(dc0);
        ss1 = wred(ss1); dq1 = wred(dq1); dc1 = wred(dc1);
        if (lane == 0) {
            float inv0 = 1.f / fmaxf(sqrtf(ss0), 1e-6f);
            float inv1 = 1.f / fmaxf(sqrtf(ss1), 1e-6f);
            sim[n0] = dc0 * inv0;
            sim[n1] = dc1 * inv1;
            float pr0 = 2.8f * sstr[n0] + 0.9f * susg[n0] + 0.6f * (1.f - sage[n0]);
            float pr1 = 2.8f * sstr[n1] + 0.9f * susg[n1] + 0.6f * (1.f - sage[n1]);
            scores[n0] = 0.65f * dq0 * inv0 + 0.22f * pr0 + 0.08f * dg * sage[n0] + 0.05f * sg * sstr[n0];
            scores[n1] = 0.65f * dq1 * inv1 + 0.22f * pr1 + 0.08f * dg * sage[n1] + 0.05f * sg * sstr[n1];
        }
    }
    __syncthreads();

    if (tid == 0) {
        int i1 = 0;
        for (int n = 1; n < NN; n++) if (scores[n] > scores[i1]) i1 = n;
        int i2 = -1;
        for (int n = 0; n < NN; n++) {
            if (n == i1) continue;
            if (i2 < 0 || scores[n] > scores[i2]) i2 = n;
        }
        float w1 = 1.f / (1.f + expf((scores[i2] - scores[i1]) * 2.f)); // TEMP=0.5
        float w2 = 1.f - w1;
        int mi = 0;
        for (int n = 1; n < NN; n++) if (sim[n] > sim[mi]) mi = n;
        int ri = 0;
        for (int n = 1; n < NN; n++) if (repl[n] > repl[ri]) ri = n;
        bool um = sim[mi] > 0.81f;
        int target = um ? mi : ri;
        float kf = g_kf[b], cp = g_cp[b], p = g_pers[b];
        float ow = (0.1f + 0.8f * kf) * (0.55f + 0.45f * cp);
        float kmix = um ? (0.18f + 0.24f * p) : (0.78f + 0.1f * p);
        float vmix = um ? (0.34f + 0.22f * p) : (0.82f + 0.1f * p);
        bc[0] = w1; bc[1] = w2; bc[2] = ow * kmix; bc[3] = ow; bc[4] = kf; bc[5] = p;
        bci[0] = i1; bci[1] = i2; bci[2] = target;
        g_i1[b] = i1; g_i2[b] = i2; g_tg[b] = target;
        g_w1[b] = w1; g_w2[b] = w2; g_ovm[b] = ow * vmix;
    }
    __syncthreads();

    const float w1 = bc[0], w2 = bc[1], owk = bc[2], ow = bc[3], kf = bc[4], p = bc[5];
    const int i1 = bci[0], i2 = bci[1], target = bci[2];

    if (tid < NN) {
        int n = tid;
        out_hits[(size_t)b * NN + n] = (n == i1) ? w1 : (n == i2) ? w2 : 0.f;
        float own = (n == target) ? ow : 0.f;
        out_str[(size_t)b * NN + n] = clip01(sstr[n] * 0.97f + own * (0.55f + 0.2f * kf + 0.15f * p));
        out_usg[(size_t)b * NN + n] = clip01(susg[n] * 0.96f + own * (0.6f + 0.4f * dg));
        out_age[(size_t)b * NN + n] = clip01((sage[n] + 0.02f) * (1.f - 0.85f * own));
    }

    if (tid >= 128) {
        int t = tid - 128;
        float4 v = kin[target * 128 + t];       // L2-hot
        float4 c = ((const float4*)sck)[t];
        v.x += owk * (c.x - v.x);
        v.y += owk * (c.y - v.y);
        v.z += owk * (c.z - v.z);
        v.w += owk * (c.w - v.w);
        kout[target * 128 + t] = v;
    }
}

// ============================================================================
// K4a: pure values copy (no dependencies — side stream). Deep MLP (8 in flight).
// ============================================================================
__global__ __launch_bounds__(256) void k4a_copy(
    const float* __restrict__ svals, float* __restrict__ out_vals)
{
    const int b = blockIdx.x;
    const int tid = threadIdx.x;
    const float4* src = (const float4*)(svals + (size_t)b * NN * DD);
    float4* dst = (float4*)(out_vals + (size_t)b * NN * DD);
    #pragma unroll
    for (int o = 0; o < 4; o++) {
        int i = tid + o * 2048;
        float4 v[8];
        #pragma unroll
        for (int j = 0; j < 8; j++) v[j] = src[i + j * 256];
        #pragma unroll
        for (int j = 0; j < 8; j++) dst[i + j * 256] = v[j];
    }
}

// ============================================================================
// K4b: target value-row blend + read_out (after K3, K4a, K2c).
// ============================================================================
__global__ __launch_bounds__(256) void k4b_fixup(
    const float* __restrict__ svals,
    float* __restrict__ out_vals, float* __restrict__ out_read)
{
    const int b = blockIdx.x;
    const int tid = threadIdx.x;
    const float4* src = (const float4*)(svals + (size_t)b * NN * DD);
    float4* dst = (float4*)(out_vals + (size_t)b * NN * DD);

    if (tid < 128) {
        const int target = g_tg[b];
        const float ovm = g_ovm[b];
        float4 v = src[target * 128 + tid];
        float4 c = ((const float4*)(g_cv + (size_t)b * DD))[tid];
        v.x += ovm * (c.x - v.x);
        v.y += ovm * (c.y - v.y);
        v.z += ovm * (c.z - v.z);
        v.w += ovm * (c.w - v.w);
        dst[target * 128 + tid] = v;
    } else {
        const int t = tid - 128;
        const int i1 = g_i1[b], i2 = g_i2[b];
        const float w1 = g_w1[b], w2 = g_w2[b];
        float4 a = src[i1 * 128 + t];
        float4 c2 = src[i2 * 128 + t];
        float4 o;
        o.x = w1 * a.x + w2 * c2.x;
        o.y = w1 * a.y + w2 * c2.y;
        o.z = w1 * a.z + w2 * c2.z;
        o.w = w1 * a.w + w2 * c2.w;
        ((float4*)(out_read + (size_t)b * DD))[t] = o;
    }
}

// ============================================================================
extern "C" void kernel_launch(void* const* d_in, const int* in_sizes, int n_in,
                              void* d_out, int out_size)
{
    const float* query_key   = (const float*)d_in[0];
    const float* delay_gate  = (const float*)d_in[1];
    const float* sal_gate    = (const float*)d_in[2];
    const float* short_keys  = (const float*)d_in[3];
    const float* short_vals  = (const float*)d_in[4];
    const float* short_str   = (const float*)d_in[5];
    const float* short_age   = (const float*)d_in[6];
    const float* short_usg   = (const float*)d_in[7];
    const float* signal      = (const float*)d_in[8];
    const float* hidden      = (const float*)d_in[9];
    const float* branch      = (const float*)d_in[10];
    const float* entropy     = (const float*)d_in[11];
    const float* ep_keys     = (const float*)d_in[12];
    const float* ep_vals     = (const float*)d_in[13];
    const float* ep_str      = (const float*)d_in[14];
    const float* ep_hits     = (const float*)d_in[15];
    const float* ep_age      = (const float*)d_in[16];
    const float* key_W       = (const float*)d_in[17];
    const float* key_b       = (const float*)d_in[18];
    const float* val_W       = (const float*)d_in[19];
    const float* val_b       = (const float*)d_in[20];
    const float* fg_W        = (const float*)d_in[21];
    const float* fg_b        = (const float*)d_in[22];
    const float* pg_W        = (const float*)d_in[23];
    const float* pg_b        = (const float*)d_in[24];
    const float* cg_W        = (const float*)d_in[25];
    const float* cg_b        = (const float*)d_in[26];

    float* out = (float*)d_out;
    float* o_read = out;                              // B*D
    float* o_hits = o_read + (size_t)BB * DD;         // B*N
    float* o_keys = o_hits + (size_t)BB * NN;         // B*N*D
    float* o_vals = o_keys + (size_t)BB * NN * DD;    // B*N*D
    float* o_str  = o_vals + (size_t)BB * NN * DD;    // B*N
    float* o_age  = o_str  + (size_t)BB * NN;         // B*N
    float* o_usg  = o_age  + (size_t)BB * NN;         // B*N

    const int k1_smem_key = 15360 * (int)sizeof(float);   // 61440 B
    const int k1_smem_val = 7680 * (int)sizeof(float);    // 30720 B

    static bool init_done = false;
    static cudaStream_t sA, sB, sC;
    static cudaEvent_t e0, eA, eB, eC;
    if (!init_done) {
        cudaStreamCreateWithFlags(&sA, cudaStreamNonBlocking);
        cudaStreamCreateWithFlags(&sB, cudaStreamNonBlocking);
        cudaStreamCreateWithFlags(&sC, cudaStreamNonBlocking);
        cudaEventCreateWithFlags(&e0, cudaEventDisableTiming);
        cudaEventCreateWithFlags(&eA, cudaEventDisableTiming);
        cudaEventCreateWithFlags(&eB, cudaEventDisableTiming);
        cudaEventCreateWithFlags(&eC, cudaEventDisableTiming);
        cudaFuncSetAttribute(k1_gemm<true>,
                             cudaFuncAttributeMaxDynamicSharedMemorySize, k1_smem_key);
        cudaFuncSetAttribute(k1_gemm<false>,
                             cudaFuncAttributeMaxDynamicSharedMemorySize, k1_smem_val);
        init_done = true;
    }

    // fork
    cudaEventRecord(e0, 0);
    cudaStreamWaitEvent(sA, e0, 0);
    cudaStreamWaitEvent(sB, e0, 0);
    cudaStreamWaitEvent(sC, e0, 0);

    // critical path: key-half GEMM, K-split into 2 parts (z-dim) = 256 blocks
    dim3 gk(DD / 128, BB / 64, 2);   // (4, 32, 2)
    k1_gemm<true><<<gk, 256, k1_smem_key>>>(signal, hidden, key_W, 0);

    // k2a early (k3 needs it), co-resident with the GEMM (tiny smem)
    k2a_select<<<BB, 256, 0, sB>>>(ep_vals, ep_str, ep_hits, ep_age,
                                   signal, hidden, branch, entropy, delay_gate,
                                   fg_W, fg_b, pg_W, pg_b, cg_W, cg_b);
    cudaEventRecord(eB, sB);

    // values copy streams DRAM while the tensor pipes grind the GEMM
    k4a_copy<<<BB, 256, 0, sA>>>(short_vals, o_vals);
    cudaEventRecord(eA, sA);

    // value-half GEMM (single tf32, compact smem) — needed only by k2c/k4b
    k1_gemm<false><<<gk, 256, k1_smem_val, sC>>>(signal, hidden, val_W, DD);

    // candidate_value on sC (needs k1_val [same stream] + k2a)
    cudaStreamWaitEvent(sC, eB, 0);
    k2c_val<<<BB, 256, 0, sC>>>(ep_vals, val_b);
    cudaEventRecord(eC, sC);

    // main: k3 needs k1_key (same stream) + k2a
    cudaStreamWaitEvent(0, eB, 0);
    k3_keys<<<BB, 256>>>(query_key, delay_gate, sal_gate, short_keys, ep_keys,
                         key_b, short_str, short_age, short_usg,
                         o_hits, o_keys, o_str, o_age, o_usg);

    // join copy + candidate_value, then fix up target row + read_out
    cudaStreamWaitEvent(0, eA, 0);
    cudaStreamWaitEvent(0, eC, 0);
    k4b_fixup<<<BB, 256>>>(short_vals, o_vals, o_read);
}